// round 16
// baseline (speedup 1.0000x reference)
#include <cuda_runtime.h>
#include <cuda_bf16.h>
#include <math.h>
#include <stdint.h>

#define N_NODES 50000
#define N_EDGES 800000

__device__ int   g_counts[N_NODES];
__device__ int   g_offsets[N_NODES + 1];
__device__ int   g_cursor[N_NODES];
__device__ int   g_csr[N_EDGES];
__device__ float g_h64[(size_t)N_NODES * 64];
__device__ __nv_bfloat16 g_xf[(size_t)N_NODES * 256];
__device__ float g_hA [(size_t)N_NODES * 256];
__device__ float g_hB [(size_t)N_NODES * 256];
__device__ float g_esrc[N_NODES * 4];
__device__ float g_edst[N_NODES * 4];
__device__ float g_pool[64];

// ---------------- CSR build ------------------------------------------------
__global__ void zero_kernel() {
    int i = blockIdx.x * blockDim.x + threadIdx.x;
    if (i < N_NODES) g_counts[i] = 0;
    if (i < 64) g_pool[i] = 0.f;
}

__global__ void hist_kernel(const int* __restrict__ dst) {
    int i = blockIdx.x * blockDim.x + threadIdx.x;
    if (i < N_EDGES) atomicAdd(&g_counts[dst[i]], 1);
}

__global__ void scan_kernel() {
    __shared__ int ssum[1024];
    int t = threadIdx.x;
    const int CH = (N_NODES + 1023) / 1024;
    int base = t * CH;
    int s = 0;
    for (int c = 0; c < CH; c++) {
        int idx = base + c;
        if (idx < N_NODES) s += g_counts[idx];
    }
    ssum[t] = s;
    __syncthreads();
    for (int off = 1; off < 1024; off <<= 1) {
        int v = (t >= off) ? ssum[t - off] : 0;
        __syncthreads();
        ssum[t] += v;
        __syncthreads();
    }
    int run = (t == 0) ? 0 : ssum[t - 1];
    for (int c = 0; c < CH; c++) {
        int idx = base + c;
        if (idx < N_NODES) {
            g_offsets[idx] = run;
            g_cursor[idx]  = run;
            run += g_counts[idx];
        }
    }
    if (t == 1023) g_offsets[N_NODES] = ssum[1023];
}

__global__ void scatter_kernel(const int* __restrict__ src, const int* __restrict__ dst) {
    int i = blockIdx.x * blockDim.x + threadIdx.x;
    if (i < N_EDGES) {
        int p = atomicAdd(&g_cursor[dst[i]], 1);
        g_csr[p] = src[i];
    }
}

// ---------------- TF32 tensor-core GEMM, 128x128 tile, double-buffered ------
// mode 0: plain bf16 store to Cb; mode 1: fp32 store +bias+elu.
__device__ __forceinline__ float tf32r(float x) {
    float y;
    asm("cvt.rna.tf32.f32 %0, %1;" : "=f"(y) : "f"(x));
    return y;
}

__device__ __forceinline__ void mma_tf32(float* c, const uint32_t* a, uint32_t b0, uint32_t b1) {
    asm volatile(
        "mma.sync.aligned.m16n8k8.row.col.f32.tf32.tf32.f32 "
        "{%0,%1,%2,%3},{%4,%5,%6,%7},{%8,%9},{%0,%1,%2,%3};"
        : "+f"(c[0]), "+f"(c[1]), "+f"(c[2]), "+f"(c[3])
        : "r"(a[0]), "r"(a[1]), "r"(a[2]), "r"(a[3]), "r"(b0), "r"(b1));
}

__global__ __launch_bounds__(256) void tf32gemm_kernel(
        const float* __restrict__ A, const float* __restrict__ B,
        const float* __restrict__ bias, float* __restrict__ C,
        __nv_bfloat16* __restrict__ Cb,
        int M, int N, int K, int mode) {
    const int BM = 128, BN = 128, BK = 16;
    __shared__ float As[2][BK][BM + 4];
    __shared__ float Bs[2][BK][BN + 4];
    int tx = threadIdx.x;
    int bm = blockIdx.y * BM;
    int bn = blockIdx.x * BN;
    int wid = tx >> 5, lane = tx & 31;
    int wm = (wid >> 1) * 32;          // 4 warps along M (0,32,64,96)
    int wn = (wid & 1) * 64;           // 2 warps along N (0,64)
    const int gid = lane >> 2;         // 0..7
    const int tig = lane & 3;          // 0..3

    float acc[2][8][4];
#pragma unroll
    for (int mt = 0; mt < 2; mt++)
#pragma unroll
        for (int nt = 0; nt < 8; nt++)
#pragma unroll
            for (int q = 0; q < 4; q++) acc[mt][nt][q] = 0.f;

    const float4 z4 = make_float4(0.f, 0.f, 0.f, 0.f);
    float4 pa[2], pb[2];

    // A-load map: idx = tx + q*256 -> row = idx>>2 (0..127), kq = (idx&3)*4
    // B-load map: idx = tx + q*256 -> br  = idx>>5 (0..15),  bc = (idx&31)*4
#pragma unroll
    for (int q = 0; q < 2; q++) {
        int idx = tx + q * 256;
        int row = idx >> 2, kq = (idx & 3) * 4;
        int gm = bm + row;
        pa[q] = (gm < M) ? *(const float4*)&A[(size_t)gm * K + kq] : z4;
    }
#pragma unroll
    for (int q = 0; q < 2; q++) {
        int idx = tx + q * 256;
        int br = idx >> 5, bc = (idx & 31) * 4;
        pb[q] = (bn + bc < N) ? *(const float4*)&B[(size_t)br * N + bn + bc] : z4;
    }

    // commit tile 0 into buffer 0
#pragma unroll
    for (int q = 0; q < 2; q++) {
        int idx = tx + q * 256;
        int row = idx >> 2, kq = (idx & 3) * 4;
        As[0][kq + 0][row] = tf32r(pa[q].x);
        As[0][kq + 1][row] = tf32r(pa[q].y);
        As[0][kq + 2][row] = tf32r(pa[q].z);
        As[0][kq + 3][row] = tf32r(pa[q].w);
    }
#pragma unroll
    for (int q = 0; q < 2; q++) {
        int idx = tx + q * 256;
        int br = idx >> 5, bc = (idx & 31) * 4;
        Bs[0][br][bc + 0] = tf32r(pb[q].x);
        Bs[0][br][bc + 1] = tf32r(pb[q].y);
        Bs[0][br][bc + 2] = tf32r(pb[q].z);
        Bs[0][br][bc + 3] = tf32r(pb[q].w);
    }
    __syncthreads();

    const int NT = K / BK;
    for (int t = 0; t < NT; t++) {
        int cur = t & 1;
        bool has_next = (t + 1 < NT);

        if (has_next) {
            int kk = (t + 1) * BK;
#pragma unroll
            for (int q = 0; q < 2; q++) {
                int idx = tx + q * 256;
                int row = idx >> 2, kq = (idx & 3) * 4;
                int gm = bm + row;
                pa[q] = (gm < M) ? *(const float4*)&A[(size_t)gm * K + kk + kq] : z4;
            }
#pragma unroll
            for (int q = 0; q < 2; q++) {
                int idx = tx + q * 256;
                int br = idx >> 5, bc = (idx & 31) * 4;
                pb[q] = (bn + bc < N) ? *(const float4*)&B[(size_t)(kk + br) * N + bn + bc] : z4;
            }
        }

        // compute: 2 k-steps of 8
#pragma unroll
        for (int ks = 0; ks < 2; ks++) {
            int kb = ks * 8;
            uint32_t af[2][4];
#pragma unroll
            for (int mt = 0; mt < 2; mt++) {
                int r = wm + mt * 16 + gid;
                af[mt][0] = __float_as_uint(As[cur][kb + tig][r]);
                af[mt][1] = __float_as_uint(As[cur][kb + tig][r + 8]);
                af[mt][2] = __float_as_uint(As[cur][kb + tig + 4][r]);
                af[mt][3] = __float_as_uint(As[cur][kb + tig + 4][r + 8]);
            }
#pragma unroll
            for (int nt = 0; nt < 8; nt++) {
                int c = wn + nt * 8 + gid;
                uint32_t b0 = __float_as_uint(Bs[cur][kb + tig][c]);
                uint32_t b1 = __float_as_uint(Bs[cur][kb + tig + 4][c]);
                mma_tf32(acc[0][nt], af[0], b0, b1);
                mma_tf32(acc[1][nt], af[1], b0, b1);
            }
        }

        if (has_next) {
            int nxt = cur ^ 1;
#pragma unroll
            for (int q = 0; q < 2; q++) {
                int idx = tx + q * 256;
                int row = idx >> 2, kq = (idx & 3) * 4;
                As[nxt][kq + 0][row] = tf32r(pa[q].x);
                As[nxt][kq + 1][row] = tf32r(pa[q].y);
                As[nxt][kq + 2][row] = tf32r(pa[q].z);
                As[nxt][kq + 3][row] = tf32r(pa[q].w);
            }
#pragma unroll
            for (int q = 0; q < 2; q++) {
                int idx = tx + q * 256;
                int br = idx >> 5, bc = (idx & 31) * 4;
                Bs[nxt][br][bc + 0] = tf32r(pb[q].x);
                Bs[nxt][br][bc + 1] = tf32r(pb[q].y);
                Bs[nxt][br][bc + 2] = tf32r(pb[q].z);
                Bs[nxt][br][bc + 3] = tf32r(pb[q].w);
            }
        }
        __syncthreads();
    }

#pragma unroll
    for (int mt = 0; mt < 2; mt++) {
#pragma unroll
        for (int half = 0; half < 2; half++) {
            int m = bm + wm + mt * 16 + gid + half * 8;
            if (m >= M) continue;
#pragma unroll
            for (int nt = 0; nt < 8; nt++) {
                int n = bn + wn + nt * 8 + 2 * tig;
                if (n >= N) continue;
                float v0 = acc[mt][nt][half * 2 + 0];
                float v1 = acc[mt][nt][half * 2 + 1];
                if (mode == 1) {
                    v0 += bias[n];
                    v1 += bias[n + 1];
                    v0 = v0 > 0.f ? v0 : expm1f(v0);
                    v1 = v1 > 0.f ? v1 : expm1f(v1);
                    *(float2*)&C[(size_t)m * N + n] = make_float2(v0, v1);
                } else {
                    *(__nv_bfloat162*)&Cb[(size_t)m * N + n] = __floats2bfloat162_rn(v0, v1);
                }
            }
        }
    }
}

// ---------------- attention logits: e_src / e_dst (bf16 features) ----------
__device__ __forceinline__ float2 b2f(uint32_t u) {
    __nv_bfloat162 h;
    *reinterpret_cast<uint32_t*>(&h) = u;
    return __bfloat1622float2(h);
}

template <int H, int D>
__global__ void compute_e_kernel(const __nv_bfloat16* __restrict__ xf,
                                 const float* __restrict__ a_s,
                                 const float* __restrict__ a_d) {
    constexpr int F = H * D;
    constexpr int FP = F / 32;
    int gw = (blockIdx.x * blockDim.x + threadIdx.x) >> 5;
    int lane = threadIdx.x & 31;
    if (gw >= N_NODES) return;
    const __nv_bfloat16* xr = xf + (size_t)gw * F;
    float ps = 0.f, pd = 0.f;
    if constexpr (FP == 8) {
        uint4 r = ((const uint4*)xr)[lane];
        float2 f0 = b2f(r.x), f1 = b2f(r.y), f2 = b2f(r.z), f3 = b2f(r.w);
        float vv[8] = {f0.x, f0.y, f1.x, f1.y, f2.x, f2.y, f3.x, f3.y};
#pragma unroll
        for (int q = 0; q < 8; q++) {
            int f = lane * 8 + q;
            ps += vv[q] * a_s[f];
            pd += vv[q] * a_d[f];
        }
    } else {
        uint32_t r = ((const uint32_t*)xr)[lane];
        float2 f = b2f(r);
        int f0 = lane * 2;
        ps += f.x * a_s[f0] + f.y * a_s[f0 + 1];
        pd += f.x * a_d[f0] + f.y * a_d[f0 + 1];
    }
    constexpr int G = 32 / H;
#pragma unroll
    for (int off = G >> 1; off; off >>= 1) {
        ps += __shfl_down_sync(0xffffffffu, ps, off);
        pd += __shfl_down_sync(0xffffffffu, pd, off);
    }
    if ((lane & (G - 1)) == 0) {
        int h = lane / G;
        g_esrc[gw * H + h] = ps;
        g_edst[gw * H + h] = pd;
    }
}

// ---------------- GAT aggregation (no max-shift, smem-staged, pipelined) ---
template <int H, int D>
__global__ __launch_bounds__(256) void gat_agg_kernel(
        const __nv_bfloat16* __restrict__ xf,
        const float* __restrict__ bias,
        float* __restrict__ out) {
    constexpr int F = H * D;
    constexpr int FP = F / 32;
    __shared__ float swv[8][32][H];
    __shared__ int   ssc[8][32];

    int wslot = threadIdx.x >> 5;
    int gw = (blockIdx.x * blockDim.x + threadIdx.x) >> 5;
    int lane = threadIdx.x & 31;
    if (gw >= N_NODES) return;
    const int i = gw;
    const int beg = g_offsets[i], end = g_offsets[i + 1];

    float edst_i[H], wself[H];
#pragma unroll
    for (int h = 0; h < H; h++) {
        edst_i[h] = g_edst[i * H + h];
        float v = g_esrc[i * H + h] + edst_i[h];
        v = v > 0.f ? v : 0.2f * v;
        wself[h] = __expf(v);
    }

    float acc[FP];
#pragma unroll
    for (int q = 0; q < FP; q++) acc[q] = 0.f;
    float ssum[H];
#pragma unroll
    for (int h = 0; h < H; h++) ssum[h] = 0.f;
    const int myh = (lane * FP) / D;

    for (int base = beg; base < end; base += 32) {
        int k = base + lane;
        int cnt = min(32, end - base);
        if (k < end) {
            int s = g_csr[k];
            ssc[wslot][lane] = s;
            float wv[H];
#pragma unroll
            for (int h = 0; h < H; h++) {
                float v = g_esrc[s * H + h] + edst_i[h];
                v = v > 0.f ? v : 0.2f * v;
                float ww = __expf(v);
                wv[h] = ww;
                ssum[h] += ww;
            }
            if constexpr (H == 4)
                *(float4*)&swv[wslot][lane][0] = make_float4(wv[0], wv[1], wv[2], wv[3]);
            else
                swv[wslot][lane][0] = wv[0];
        }
        __syncwarp();

        if constexpr (FP == 8) {
            uint4 cur;
            {
                int s0 = ssc[wslot][0];
                cur = ((const uint4*)(xf + (size_t)s0 * F))[lane];
            }
            for (int j = 0; j < cnt; j++) {
                float wh = swv[wslot][j][myh];
                uint4 nxt = cur;
                if (j + 1 < cnt) {
                    int sn = ssc[wslot][j + 1];
                    nxt = ((const uint4*)(xf + (size_t)sn * F))[lane];
                }
                float2 f0 = b2f(cur.x), f1 = b2f(cur.y), f2 = b2f(cur.z), f3 = b2f(cur.w);
                acc[0] += wh * f0.x; acc[1] += wh * f0.y;
                acc[2] += wh * f1.x; acc[3] += wh * f1.y;
                acc[4] += wh * f2.x; acc[5] += wh * f2.y;
                acc[6] += wh * f3.x; acc[7] += wh * f3.y;
                cur = nxt;
            }
        } else {
            uint32_t cur;
            {
                int s0 = ssc[wslot][0];
                cur = ((const uint32_t*)(xf + (size_t)s0 * F))[lane];
            }
            for (int j = 0; j < cnt; j++) {
                float wh = swv[wslot][j][0];
                uint32_t nxt = cur;
                if (j + 1 < cnt) {
                    int sn = ssc[wslot][j + 1];
                    nxt = ((const uint32_t*)(xf + (size_t)sn * F))[lane];
                }
                float2 f = b2f(cur);
                acc[0] += wh * f.x; acc[1] += wh * f.y;
                cur = nxt;
            }
        }
        __syncwarp();
    }

#pragma unroll
    for (int h = 0; h < H; h++)
#pragma unroll
        for (int off = 16; off; off >>= 1)
            ssum[h] += __shfl_xor_sync(0xffffffffu, ssum[h], off);
#pragma unroll
    for (int h = 0; h < H; h++) ssum[h] += wself[h];

    {
        float wh;
        if constexpr (H == 4)
            wh = (myh == 0) ? wself[0] : (myh == 1) ? wself[1] : (myh == 2) ? wself[2] : wself[3];
        else
            wh = wself[0];
        const __nv_bfloat16* xr = xf + (size_t)i * F;
        if constexpr (FP == 8) {
            uint4 r = ((const uint4*)xr)[lane];
            float2 f0 = b2f(r.x), f1 = b2f(r.y), f2 = b2f(r.z), f3 = b2f(r.w);
            acc[0] += wh * f0.x; acc[1] += wh * f0.y;
            acc[2] += wh * f1.x; acc[3] += wh * f1.y;
            acc[4] += wh * f2.x; acc[5] += wh * f2.y;
            acc[6] += wh * f3.x; acc[7] += wh * f3.y;
        } else {
            uint32_t r = ((const uint32_t*)xr)[lane];
            float2 f = b2f(r);
            acc[0] += wh * f.x; acc[1] += wh * f.y;
        }
    }

    float denom;
    if constexpr (H == 4)
        denom = (myh == 0) ? ssum[0] : (myh == 1) ? ssum[1] : (myh == 2) ? ssum[2] : ssum[3];
    else
        denom = ssum[0];
    float inv = 1.f / denom;
#pragma unroll
    for (int q = 0; q < FP; q++) {
        int f = lane * FP + q;
        float v = acc[q] * inv + bias[f];
        v = v > 0.f ? v : expm1f(v);
        out[(size_t)i * F + f] = v;
    }
}

// ---------------- global mean pool + output projection ---------------------
__global__ void pool_kernel(const float* __restrict__ h) {
    __shared__ float sacc[64];
    int t = threadIdx.x;
    if (t < 64) sacc[t] = 0.f;
    __syncthreads();
    int col = t & 63;
    int rpb = blockDim.x >> 6;
    float a = 0.f;
    for (int r = blockIdx.x * rpb + (t >> 6); r < N_NODES; r += gridDim.x * rpb)
        a += h[(size_t)r * 64 + col];
    atomicAdd(&sacc[col], a);
    __syncthreads();
    if (t < 64) atomicAdd(&g_pool[t], sacc[t]);
}

__global__ void final_kernel(const float* __restrict__ w_out,
                             const float* __restrict__ b_out,
                             float* __restrict__ out) {
    int j = threadIdx.x;
    float s = b_out[j];
    const float invn = 1.f / (float)N_NODES;
    for (int k = 0; k < 64; k++)
        s += g_pool[k] * invn * w_out[k * 128 + j];
    out[j] = s;
}

// ---------------- launcher -------------------------------------------------
extern "C" void kernel_launch(void* const* d_in, const int* in_sizes, int n_in,
                              void* d_out, int out_size) {
    const float* x     = (const float*)d_in[0];
    const int*   ei    = (const int*)d_in[1];
    const int*   src   = ei;
    const int*   dst   = ei + N_EDGES;
    const float* w_in  = (const float*)d_in[2];
    const float* b_in  = (const float*)d_in[3];
    const float* W0    = (const float*)d_in[4];
    const float* as0   = (const float*)d_in[5];
    const float* ad0   = (const float*)d_in[6];
    const float* bb0   = (const float*)d_in[7];
    const float* W1    = (const float*)d_in[8];
    const float* as1   = (const float*)d_in[9];
    const float* ad1   = (const float*)d_in[10];
    const float* bb1   = (const float*)d_in[11];
    const float* W2    = (const float*)d_in[12];
    const float* as2   = (const float*)d_in[13];
    const float* ad2   = (const float*)d_in[14];
    const float* bb2   = (const float*)d_in[15];
    const float* w_out = (const float*)d_in[16];
    const float* b_out = (const float*)d_in[17];
    float* out = (float*)d_out;

    void *p_h64, *p_xf, *p_hA, *p_hB;
    cudaGetSymbolAddress(&p_h64, g_h64);
    cudaGetSymbolAddress(&p_xf,  g_xf);
    cudaGetSymbolAddress(&p_hA,  g_hA);
    cudaGetSymbolAddress(&p_hB,  g_hB);
    float* h64 = (float*)p_h64;
    __nv_bfloat16* xf = (__nv_bfloat16*)p_xf;
    float* hA  = (float*)p_hA;
    float* hB  = (float*)p_hB;

    const int EB = (N_EDGES + 255) / 256;
    const int NB = (N_NODES + 255) / 256;
    const int MY = (N_NODES + 127) / 128;
    const int WARPB = N_NODES / 8;

    zero_kernel<<<NB, 256>>>();
    hist_kernel<<<EB, 256>>>(dst);
    scan_kernel<<<1, 1024>>>();
    scatter_kernel<<<EB, 256>>>(src, dst);

    tf32gemm_kernel<<<dim3(1, MY), 256>>>(x, w_in, b_in, h64, nullptr,
                                          N_NODES, 64, 256, 1);

    tf32gemm_kernel<<<dim3(2, MY), 256>>>(h64, W0, nullptr, nullptr, xf,
                                          N_NODES, 256, 64, 0);
    compute_e_kernel<4, 64><<<WARPB, 256>>>(xf, as0, ad0);
    gat_agg_kernel<4, 64><<<WARPB, 256>>>(xf, bb0, hA);

    tf32gemm_kernel<<<dim3(2, MY), 256>>>(hA, W1, nullptr, nullptr, xf,
                                          N_NODES, 256, 256, 0);
    compute_e_kernel<4, 64><<<WARPB, 256>>>(xf, as1, ad1);
    gat_agg_kernel<4, 64><<<WARPB, 256>>>(xf, bb1, hB);

    tf32gemm_kernel<<<dim3(1, MY), 256>>>(hB, W2, nullptr, nullptr, xf,
                                          N_NODES, 64, 256, 0);
    compute_e_kernel<1, 64><<<WARPB, 256>>>(xf, as2, ad2);
    gat_agg_kernel<1, 64><<<WARPB, 256>>>(xf, bb2, h64);

    pool_kernel<<<256, 256>>>(h64);
    final_kernel<<<1, 128>>>(w_out, b_out, out);
}